// round 3
// baseline (speedup 1.0000x reference)
#include <cuda_runtime.h>

#define FEATURES 2048
#define SCALE 4.0f

// out = sigmoid(SCALE * (x * w[f] + b[f])), elementwise over [N, FEATURES] fp32.
// Pure HBM-streaming: float4 loads/stores, w/b broadcast from L1 (8 KB each).
__global__ void __launch_bounds__(256) onetoone_sigmoid_kernel(
    const float4* __restrict__ x,
    const float4* __restrict__ w,
    const float4* __restrict__ b,
    float4* __restrict__ out,
    int total4)
{
    int i = blockIdx.x * blockDim.x + threadIdx.x;
    if (i >= total4) return;

    // FEATURES/4 = 512 float4 per row; feature index for this vec4
    int fi = i & (FEATURES / 4 - 1);

    float4 xv = x[i];
    float4 wv = __ldg(&w[fi]);
    float4 bv = __ldg(&b[fi]);

    float4 r;
    {
        float z;
        z = SCALE * fmaf(xv.x, wv.x, bv.x);
        r.x = 1.0f / (1.0f + __expf(-z));
        z = SCALE * fmaf(xv.y, wv.y, bv.y);
        r.y = 1.0f / (1.0f + __expf(-z));
        z = SCALE * fmaf(xv.z, wv.z, bv.z);
        r.z = 1.0f / (1.0f + __expf(-z));
        z = SCALE * fmaf(xv.w, wv.w, bv.w);
        r.w = 1.0f / (1.0f + __expf(-z));
    }
    out[i] = r;
}

extern "C" void kernel_launch(void* const* d_in, const int* in_sizes, int n_in,
                              void* d_out, int out_size)
{
    const float4* x = (const float4*)d_in[0];   // input  [N, FEATURES] fp32
    const float4* w = (const float4*)d_in[1];   // weight [FEATURES]    fp32
    const float4* b = (const float4*)d_in[2];   // bias   [FEATURES]    fp32
    float4* out = (float4*)d_out;               // output [N, FEATURES] fp32

    int total4 = out_size / 4;                  // 32768*2048/4 = 16,777,216
    int threads = 256;
    int blocks = (total4 + threads - 1) / threads;
    onetoone_sigmoid_kernel<<<blocks, threads>>>(x, w, b, out, total4);
}

// round 4
// speedup vs baseline: 1.0029x; 1.0029x over previous
#include <cuda_runtime.h>

#define FEATURES 2048
#define SCALE 4.0f

// out = sigmoid(SCALE * (x * w[f] + b[f])), elementwise over [N, FEATURES] fp32.
// Pure HBM-streaming: float4 loads/stores, w/b broadcast from L1 (8 KB each).
__global__ void __launch_bounds__(256) onetoone_sigmoid_kernel(
    const float4* __restrict__ x,
    const float4* __restrict__ w,
    const float4* __restrict__ b,
    float4* __restrict__ out,
    int total4)
{
    int i = blockIdx.x * blockDim.x + threadIdx.x;
    if (i >= total4) return;

    // FEATURES/4 = 512 float4 per row; feature index for this vec4
    int fi = i & (FEATURES / 4 - 1);

    float4 xv = x[i];
    float4 wv = __ldg(&w[fi]);
    float4 bv = __ldg(&b[fi]);

    float4 r;
    {
        float z;
        z = SCALE * fmaf(xv.x, wv.x, bv.x);
        r.x = 1.0f / (1.0f + __expf(-z));
        z = SCALE * fmaf(xv.y, wv.y, bv.y);
        r.y = 1.0f / (1.0f + __expf(-z));
        z = SCALE * fmaf(xv.z, wv.z, bv.z);
        r.z = 1.0f / (1.0f + __expf(-z));
        z = SCALE * fmaf(xv.w, wv.w, bv.w);
        r.w = 1.0f / (1.0f + __expf(-z));
    }
    out[i] = r;
}

extern "C" void kernel_launch(void* const* d_in, const int* in_sizes, int n_in,
                              void* d_out, int out_size)
{
    const float4* x = (const float4*)d_in[0];   // input  [N, FEATURES] fp32
    const float4* w = (const float4*)d_in[1];   // weight [FEATURES]    fp32
    const float4* b = (const float4*)d_in[2];   // bias   [FEATURES]    fp32
    float4* out = (float4*)d_out;               // output [N, FEATURES] fp32

    int total4 = out_size / 4;                  // 32768*2048/4 = 16,777,216
    int threads = 256;
    int blocks = (total4 + threads - 1) / threads;
    onetoone_sigmoid_kernel<<<blocks, threads>>>(x, w, b, out, total4);
}